// round 17
// baseline (speedup 1.0000x reference)
#include <cuda_runtime.h>
#include <cuda_bf16.h>
#include <cstdint>

// AFM forward, algebraically collapsed (softmax over size-1 axis == 1):
//   x[b]   = 0.5*(||sum_f emb_f||^2 - sum_f ||emb_f||^2)
//   out[b] = sigmoid(x[b]*out_kernel + out_bias)
//
// R17 probe: 256-bit gathers (ld.global.nc.v8.f32, Blackwell LDG.E.256).
// 2 lanes per embedding (32B halves) -> one warp covers 16 embeddings per
// instruction: 2 gather instructions + 2 id loads per warp instead of 4+4,
// for the IDENTICAL 106,496 x 64B transactions. Tests whether the
// outstanding-miss cap is per-instruction (scoreboard/L1tex slots -> ~2x
// concurrency -> ~4.5-5.5us) or per-transaction (neutral -> floor stands).
// Shape otherwise: ONE WARP PER ROW, 1024 CTAs x 128 threads.

#define B_ROWS   4096
#define N_SPARSE 26
#define VOCAB    100000

struct F8 { float v[8]; };

__device__ __forceinline__ F8 ldg_256(const float* p) {
    F8 r;
    asm("ld.global.nc.L2::64B.v8.f32 {%0,%1,%2,%3,%4,%5,%6,%7}, [%8];"
        : "=f"(r.v[0]), "=f"(r.v[1]), "=f"(r.v[2]), "=f"(r.v[3]),
          "=f"(r.v[4]), "=f"(r.v[5]), "=f"(r.v[6]), "=f"(r.v[7])
        : "l"(p));
    return r;
}

__global__ void __launch_bounds__(128) afm_gather_kernel(
    const int*   __restrict__ ids,      // [B, 26]
    const float* __restrict__ table,    // [26, VOCAB, 16] floats
    const float* __restrict__ out_k,    // [1]
    const float* __restrict__ out_b,    // [1]
    float*       __restrict__ out)      // [B]
{
    const unsigned FULL = 0xffffffffu;
    const int gtid = blockIdx.x * blockDim.x + threadIdx.x;
    const int row  = gtid >> 5;            // one warp per row (grid exact)
    const int lane = threadIdx.x & 31;

    const int half = lane & 1;             // which 32B half of the embedding
    const int fs   = lane >> 1;            // field slot 0..15 within round

    const int* rid = ids + row * N_SPARSE;

    const float okv = __ldg(out_k);
    const float obv = __ldg(out_b);

    // Round r covers fields r*16 + fs (round 1: fs<10 active).
    // Front-batched: 2 id loads (2-lane broadcast), then 2 LDG.256.
    int idr[2];
    #pragma unroll
    for (int r = 0; r < 2; ++r) {
        int f = r * 16 + fs;
        idr[r] = __ldg(rid + (f < N_SPARSE ? f : N_SPARSE - 1));
    }

    float S[8];
    #pragma unroll
    for (int i = 0; i < 8; ++i) S[i] = 0.f;
    float q = 0.f;

    #pragma unroll
    for (int r = 0; r < 2; ++r) {
        const int f = r * 16 + fs;
        if (f < N_SPARSE) {
            // 64B-aligned embedding; this lane's 32B half (32B-aligned).
            const float* gp = table + (size_t)f * (VOCAB * 16)
                                    + (size_t)idr[r] * 16 + half * 8;
            const F8 a = ldg_256(gp);
            #pragma unroll
            for (int i = 0; i < 8; ++i) {
                S[i] += a.v[i];
                q    += a.v[i] * a.v[i];
            }
        }
    }

    // Reduce S,q over the field slots (lane bits 1..4): 4 levels.
    #pragma unroll
    for (int d = 2; d <= 16; d <<= 1) {
        #pragma unroll
        for (int i = 0; i < 8; ++i)
            S[i] += __shfl_xor_sync(FULL, S[i], d);
        q += __shfl_xor_sync(FULL, q, d);
    }

    // Lanes 0,1 hold the per-half 8-component totals of sum_f emb_f.
    // Halves are disjoint components, so |S_full|^2 = sum over both halves.
    float t = -q;
    #pragma unroll
    for (int i = 0; i < 8; ++i) t += S[i] * S[i];
    t += __shfl_xor_sync(FULL, t, 1);

    if (lane == 0) {
        const float z = 0.5f * t * okv + obv;   // t == 2*sum_{i<j} e_i.e_j
        out[row] = 1.0f / (1.0f + __expf(-z));
    }
}

extern "C" void kernel_launch(void* const* d_in, const int* in_sizes, int n_in,
                              void* d_out, int out_size)
{
    (void)in_sizes; (void)n_in; (void)out_size;
    const int*   ids   = (const int*)  d_in[1];
    const float* table = (const float*)d_in[2];
    const float* out_k = (const float*)d_in[7];
    const float* out_b = (const float*)d_in[8];
    float*       out   = (float*)      d_out;

    const int threads = 128;                     // 4 warps = 4 rows / block
    const int blocks  = (B_ROWS * 32) / threads; // 1024 blocks, exact
    afm_gather_kernel<<<blocks, threads>>>(ids, table, out_k, out_b, out);
}